// round 2
// baseline (speedup 1.0000x reference)
#include <cuda_runtime.h>

// Batched Kalman filter: B=262144, N=8, M=4, fp32.
// One thread per batch, register-resident math; ALL gmem traffic staged through
// padded shared memory so global accesses are fully coalesced float4.
// Outputs flat: x_new[B,8], P_new[B,8,8], K[B,8,4].

constexpr int BT  = 262144;
constexpr int TPB = 128;
constexpr float EPS = 1e-6f;

// Coalesced gmem -> padded smem. E = floats per batch, S = padded row stride (odd).
template<int E, int S>
__device__ __forceinline__ void stage_in(float* sm, const float* __restrict__ g,
                                         int b0, int tid) {
    const float4* g4 = reinterpret_cast<const float4*>(g + (size_t)b0 * E);
    constexpr int TOT4 = TPB * E / 4;
#pragma unroll
    for (int i = tid; i < TOT4; i += TPB) {
        float4 v = g4[i];
        int e = i * 4;
        float* d = sm + (e / E) * S + (e % E);
        d[0] = v.x; d[1] = v.y; d[2] = v.z; d[3] = v.w;
    }
}

// Padded smem -> coalesced gmem.
template<int E, int S>
__device__ __forceinline__ void stage_out(float* __restrict__ g, const float* sm,
                                          int b0, int tid) {
    float4* g4 = reinterpret_cast<float4*>(g + (size_t)b0 * E);
    constexpr int TOT4 = TPB * E / 4;
#pragma unroll
    for (int i = tid; i < TOT4; i += TPB) {
        int e = i * 4;
        const float* s = sm + (e / E) * S + (e % E);
        g4[i] = make_float4(s[0], s[1], s[2], s[3]);
    }
}

__global__ __launch_bounds__(TPB) void kf_kernel(
    const float* __restrict__ gx, const float* __restrict__ gP,
    const float* __restrict__ gF, const float* __restrict__ gQ,
    const float* __restrict__ gz, const float* __restrict__ gH,
    const float* __restrict__ gR, float* __restrict__ out)
{
    __shared__ float buf[9472];              // 37 KB static
    const int tid = threadIdx.x;
    const int b0  = blockIdx.x * TPB;        // BT % TPB == 0, no tail

    // ---------- Phase 1: F [8x8] + x [8] ----------
    stage_in<64, 65>(buf, gF, b0, tid);
    stage_in<8, 9>(buf + 8320, gx, b0, tid);
    __syncthreads();
    float f[64];
    {
        const float* fr = buf + tid * 65;
#pragma unroll
        for (int i = 0; i < 64; ++i) f[i] = fr[i];
    }
    float x[8];
    {
        const float* xr = buf + 8320 + tid * 9;
#pragma unroll
        for (int i = 0; i < 8; ++i) x[i] = xr[i];
    }
    __syncthreads();

    // ---------- Phase 2: stage P while computing x_pred ----------
    stage_in<64, 65>(buf, gP, b0, tid);
    float xp[8];
#pragma unroll
    for (int i = 0; i < 8; ++i) {
        float s = 0.f;
#pragma unroll
        for (int j = 0; j < 8; ++j) s += f[i*8+j] * x[j];
        xp[i] = s;
    }
    __syncthreads();
    float p[64];
    {
        const float* pr = buf + tid * 65;
#pragma unroll
        for (int i = 0; i < 64; ++i) p[i] = pr[i];
    }
    __syncthreads();

    // ---------- Phase 3: stage Q while computing T = F @ P ----------
    stage_in<64, 65>(buf, gQ, b0, tid);
    float tt[64];
#pragma unroll
    for (int i = 0; i < 8; ++i) {
#pragma unroll
        for (int j = 0; j < 8; ++j) {
            float s = 0.f;
#pragma unroll
            for (int k = 0; k < 8; ++k) s += f[i*8+k] * p[k*8+j];
            tt[i*8+j] = s;
        }
    }
    __syncthreads();
    // P_pred = T @ F^T + Q   (overwrite p)
    {
        const float* qr = buf + tid * 65;
#pragma unroll
        for (int i = 0; i < 8; ++i) {
#pragma unroll
            for (int j = 0; j < 8; ++j) {
                float s = qr[i*8+j];
#pragma unroll
                for (int k = 0; k < 8; ++k) s += tt[i*8+k] * f[j*8+k];
                p[i*8+j] = s;
            }
        }
    }
    __syncthreads();

    // ---------- Phase 4: stage H [4x8], R [4x4], z [4] ----------
    stage_in<32, 33>(buf,        gH, b0, tid);
    stage_in<16, 17>(buf + 4224, gR, b0, tid);
    stage_in<4, 5>(buf + 6400, gz, b0, tid);
    __syncthreads();
    float h[32];
    {
        const float* hr = buf + tid * 33;
#pragma unroll
        for (int i = 0; i < 32; ++i) h[i] = hr[i];
    }

    // A = P_pred @ H^T  [8x4]
    float a[32];
#pragma unroll
    for (int i = 0; i < 8; ++i) {
#pragma unroll
        for (int m = 0; m < 4; ++m) {
            float s = 0.f;
#pragma unroll
            for (int j = 0; j < 8; ++j) s += p[i*8+j] * h[m*8+j];
            a[i*4+m] = s;
        }
    }

    // S = H @ A + R + EPS*I  [4x4]  (R read straight from smem)
    float s4[16];
    {
        const float* rr = buf + 4224 + tid * 17;
#pragma unroll
        for (int m = 0; m < 4; ++m) {
#pragma unroll
            for (int n = 0; n < 4; ++n) {
                float s = rr[m*4+n] + (m == n ? EPS : 0.f);
#pragma unroll
                for (int i = 0; i < 8; ++i) s += h[m*8+i] * a[i*4+n];
                s4[m*4+n] = s;
            }
        }
    }

    // Cholesky of S (SPD), unrolled
    float L00 = sqrtf(s4[0]);
    float iL00 = 1.0f / L00;
    float L10 = s4[4]  * iL00;
    float L20 = s4[8]  * iL00;
    float L30 = s4[12] * iL00;
    float L11 = sqrtf(s4[5] - L10*L10);
    float iL11 = 1.0f / L11;
    float L21 = (s4[9]  - L20*L10) * iL11;
    float L31 = (s4[13] - L30*L10) * iL11;
    float L22 = sqrtf(s4[10] - L20*L20 - L21*L21);
    float iL22 = 1.0f / L22;
    float L32 = (s4[14] - L30*L20 - L31*L21) * iL22;
    float L33 = sqrtf(s4[15] - L30*L30 - L31*L31 - L32*L32);
    float iL33 = 1.0f / L33;

    // K = A @ S^{-1} via two triangular solves per row
    float kk[32];
#pragma unroll
    for (int i = 0; i < 8; ++i) {
        float a0 = a[i*4+0], a1 = a[i*4+1], a2 = a[i*4+2], a3 = a[i*4+3];
        float w0 = a0 * iL00;
        float w1 = (a1 - L10*w0) * iL11;
        float w2 = (a2 - L20*w0 - L21*w1) * iL22;
        float w3 = (a3 - L30*w0 - L31*w1 - L32*w2) * iL33;
        float k3 = w3 * iL33;
        float k2 = (w2 - L32*k3) * iL22;
        float k1 = (w1 - L21*k2 - L31*k3) * iL11;
        float k0 = (w0 - L10*k1 - L20*k2 - L30*k3) * iL00;
        kk[i*4+0]=k0; kk[i*4+1]=k1; kk[i*4+2]=k2; kk[i*4+3]=k3;
    }

    // y = z - H @ x_pred   (z read straight from smem)
    float y[4];
    {
        const float* zr = buf + 6400 + tid * 5;
#pragma unroll
        for (int m = 0; m < 4; ++m) {
            float s = zr[m];
#pragma unroll
            for (int i = 0; i < 8; ++i) s -= h[m*8+i] * xp[i];
            y[m] = s;
        }
    }

    // x_new = x_pred + K @ y
    float xn[8];
#pragma unroll
    for (int i = 0; i < 8; ++i) {
        float s = xp[i];
#pragma unroll
        for (int m = 0; m < 4; ++m) s += kk[i*4+m] * y[m];
        xn[i] = s;
    }

    // HP = H @ P_pred  [4x8]
    float hp[32];
#pragma unroll
    for (int m = 0; m < 4; ++m) {
#pragma unroll
        for (int j = 0; j < 8; ++j) {
            float s = 0.f;
#pragma unroll
            for (int i = 0; i < 8; ++i) s += h[m*8+i] * p[i*8+j];
            hp[m*8+j] = s;
        }
    }

    // ---------- Phase 5: outputs through smem ----------
    __syncthreads();                      // all buf reads above complete
    {   // P_new = P_pred - K @ HP  -> smem rows
        float* pw = buf + tid * 65;
#pragma unroll
        for (int i = 0; i < 8; ++i) {
#pragma unroll
            for (int j = 0; j < 8; ++j) {
                float s = p[i*8+j];
#pragma unroll
                for (int m = 0; m < 4; ++m) s -= kk[i*4+m] * hp[m*8+j];
                pw[i*8+j] = s;
            }
        }
    }
    __syncthreads();
    stage_out<64, 65>(out + (size_t)8 * BT, buf, b0, tid);
    __syncthreads();                      // buf drained before reuse
    {
        float* kw = buf + tid * 33;
#pragma unroll
        for (int i = 0; i < 32; ++i) kw[i] = kk[i];
        float* xw = buf + 4224 + tid * 9;
#pragma unroll
        for (int i = 0; i < 8; ++i) xw[i] = xn[i];
    }
    __syncthreads();
    stage_out<32, 33>(out + (size_t)72 * BT, buf, b0, tid);
    stage_out<8, 9>(out, buf + 4224, b0, tid);
}

extern "C" void kernel_launch(void* const* d_in, const int* in_sizes, int n_in,
                              void* d_out, int out_size) {
    const float* x_est = (const float*)d_in[0];
    const float* P_est = (const float*)d_in[1];
    const float* F     = (const float*)d_in[2];
    const float* Q     = (const float*)d_in[3];
    const float* z     = (const float*)d_in[4];
    const float* H     = (const float*)d_in[5];
    const float* R     = (const float*)d_in[6];
    float* out = (float*)d_out;

    kf_kernel<<<BT / TPB, TPB>>>(x_est, P_est, F, Q, z, H, R, out);
}

// round 3
// speedup vs baseline: 1.1584x; 1.1584x over previous
#include <cuda_runtime.h>

// Batched Kalman filter: B=262144, N=8, M=4, fp32.
// 4 threads per batch; thread s owns rows {s, s+4}. Cross-row data exchanged
// through padded shared memory (4-thread groups never cross a warp ->
// __syncwarp only). All global traffic is coalesced float4 via smem staging.
// Outputs flat: x_new[B,8], P_new[B,8,8], K[B,8,4].

constexpr int BT  = 262144;
constexpr int TPB = 128;
constexpr int G   = 32;          // batches per block
constexpr float EPS = 1e-6f;

template<int E, int S>
__device__ __forceinline__ void stage_in(float* sm, const float* __restrict__ gp,
                                         int b0, int tid) {
    const float4* g4 = reinterpret_cast<const float4*>(gp + (size_t)b0 * E);
    constexpr int T4 = G * E / 4;
#pragma unroll
    for (int i = tid; i < T4; i += TPB) {
        float4 v = g4[i];
        int e = i * 4;
        float* d = sm + (e / E) * S + (e % E);
        d[0] = v.x; d[1] = v.y; d[2] = v.z; d[3] = v.w;
    }
}

template<int E, int S>
__device__ __forceinline__ void stage_out(float* __restrict__ gp, const float* sm,
                                          int b0, int tid) {
    float4* g4 = reinterpret_cast<float4*>(gp + (size_t)b0 * E);
    constexpr int T4 = G * E / 4;
#pragma unroll
    for (int i = tid; i < T4; i += TPB) {
        int e = i * 4;
        const float* sp = sm + (e / E) * S + (e % E);
        g4[i] = make_float4(sp[0], sp[1], sp[2], sp[3]);
    }
}

__global__ __launch_bounds__(TPB, 5) void kf_kernel(
    const float* __restrict__ gx, const float* __restrict__ gP,
    const float* __restrict__ gF, const float* __restrict__ gQ,
    const float* __restrict__ gz, const float* __restrict__ gH,
    const float* __restrict__ gR, float* __restrict__ out)
{
    __shared__ float sm[10176];      // 40.7 KB
    float* sF  = sm;                 // stride 65, 2080
    float* sP  = sm + 2080;          // stride 65
    float* sQ  = sm + 4160;          // stride 65
    float* sH  = sm + 6240;          // stride 33, 1056
    float* sR  = sm + 7296;          // stride 17, 544
    float* sx  = sm + 7840;          // stride 9,  288
    float* sz  = sm + 8128;          // stride 5,  160
    float* sA  = sm + 8288;          // stride 33, 1056 (reused for HP)
    float* sS  = sm + 9344;          // stride 17, 544
    float* sXP = sm + 9888;          // stride 9,  288

    const int tid = threadIdx.x;
    const int b0  = blockIdx.x * G;
    const int g   = tid >> 2;        // batch within block
    const int s   = tid & 3;         // sub-thread: owns rows r0=s, r1=s+4
    const int r0  = s, r1 = s + 4;

    stage_in<64, 65>(sF, gF, b0, tid);
    stage_in<8, 9>(sx, gx, b0, tid);
    stage_in<64, 65>(sP, gP, b0, tid);
    stage_in<64, 65>(sQ, gQ, b0, tid);
    stage_in<32, 33>(sH, gH, b0, tid);
    stage_in<16, 17>(sR, gR, b0, tid);
    stage_in<4, 5>(sz, gz, b0, tid);
    __syncthreads();

    float* Fb  = sF  + g * 65;
    float* Pb  = sP  + g * 65;
    float* Qb  = sQ  + g * 65;
    float* Hb  = sH  + g * 33;
    float* Rb  = sR  + g * 17;
    float* xb  = sx  + g * 9;
    float* zb  = sz  + g * 5;
    float* Ab  = sA  + g * 33;       // A exchange, later HP exchange
    float* Sb  = sS  + g * 17;
    float* XPb = sXP + g * 9;

    // ---- own F rows ----
    float f0[8], f1[8];
#pragma unroll
    for (int j = 0; j < 8; ++j) { f0[j] = Fb[r0*8+j]; f1[j] = Fb[r1*8+j]; }

    // ---- x_pred (own rows) ----
    float xp0 = 0.f, xp1 = 0.f;
#pragma unroll
    for (int j = 0; j < 8; ++j) { float xj = xb[j]; xp0 += f0[j]*xj; xp1 += f1[j]*xj; }

    // ---- T rows: T[r][:] = sum_k F[r][k] * P[k][:] ----
    float t0[8], t1[8];
#pragma unroll
    for (int j = 0; j < 8; ++j) { t0[j] = 0.f; t1[j] = 0.f; }
#pragma unroll
    for (int k = 0; k < 8; ++k) {
        float fk0 = f0[k], fk1 = f1[k];
#pragma unroll
        for (int j = 0; j < 8; ++j) {
            float pkj = Pb[k*8+j];
            t0[j] += fk0 * pkj; t1[j] += fk1 * pkj;
        }
    }

    // ---- P_pred rows: pp[r][j] = sum_k T[r][k]*F[j][k] + Q[r][j] ----
    float pp0[8], pp1[8];
#pragma unroll
    for (int j = 0; j < 8; ++j) {
        float u0 = Qb[r0*8+j], u1 = Qb[r1*8+j];
#pragma unroll
        for (int k = 0; k < 8; ++k) {
            float fjk = Fb[j*8+k];
            u0 += t0[k] * fjk; u1 += t1[k] * fjk;
        }
        pp0[j] = u0; pp1[j] = u1;
    }

    // ---- A rows: A[r][m] = sum_j pp[r][j] * H[m][j] ----
    float a0[4], a1[4];
#pragma unroll
    for (int m = 0; m < 4; ++m) {
        float u0 = 0.f, u1 = 0.f;
#pragma unroll
        for (int j = 0; j < 8; ++j) {
            float hm = Hb[m*8+j];
            u0 += pp0[j] * hm; u1 += pp1[j] * hm;
        }
        a0[m] = u0; a1[m] = u1;
    }

    // ---- exchange pp (into sP), A, xp ----
    __syncwarp();                    // group done reading original P / x / F cols
#pragma unroll
    for (int j = 0; j < 8; ++j) { Pb[r0*8+j] = pp0[j]; Pb[r1*8+j] = pp1[j]; }
#pragma unroll
    for (int m = 0; m < 4; ++m) { Ab[r0*4+m] = a0[m]; Ab[r1*4+m] = a1[m]; }
    XPb[r0] = xp0; XPb[r1] = xp1;
    __syncwarp();                    // publish

    // ---- S row s = R row + eps*I + sum_i H[s][i]*A[i][:] ; HP row s ----
    float hs[8];
#pragma unroll
    for (int i = 0; i < 8; ++i) hs[i] = Hb[s*8+i];

#pragma unroll
    for (int n = 0; n < 4; ++n) {
        float acc = Rb[s*4+n] + (n == s ? EPS : 0.f);
#pragma unroll
        for (int i = 0; i < 8; ++i) acc += hs[i] * Ab[i*4+n];
        Sb[s*4+n] = acc;
    }
    float hprow[8];
#pragma unroll
    for (int j = 0; j < 8; ++j) {
        float acc = 0.f;
#pragma unroll
        for (int i = 0; i < 8; ++i) acc += hs[i] * Pb[i*8+j];
        hprow[j] = acc;
    }
    __syncwarp();                    // all A reads done -> safe to overlay HP on A
#pragma unroll
    for (int j = 0; j < 8; ++j) Ab[s*8+j] = hprow[j];   // HP row s
    __syncwarp();                    // publish S + HP

    // ---- Cholesky of S (redundant per thread, rsqrt-based) ----
    float s00 = Sb[0];
    float s10 = Sb[4],  s11 = Sb[5];
    float s20 = Sb[8],  s21 = Sb[9],  s22 = Sb[10];
    float s30 = Sb[12], s31 = Sb[13], s32 = Sb[14], s33 = Sb[15];

    float iL00 = rsqrtf(s00);
    float L10 = s10 * iL00, L20 = s20 * iL00, L30 = s30 * iL00;
    float iL11 = rsqrtf(s11 - L10*L10);
    float L21 = (s21 - L20*L10) * iL11;
    float L31 = (s31 - L30*L10) * iL11;
    float iL22 = rsqrtf(s22 - L20*L20 - L21*L21);
    float L32 = (s32 - L30*L20 - L31*L21) * iL22;
    float iL33 = rsqrtf(s33 - L30*L30 - L31*L31 - L32*L32);

    // ---- K rows (own): solve S k = a ----
    float k0[4], k1[4];
    {
        float w0 = a0[0] * iL00;
        float w1 = (a0[1] - L10*w0) * iL11;
        float w2 = (a0[2] - L20*w0 - L21*w1) * iL22;
        float w3 = (a0[3] - L30*w0 - L31*w1 - L32*w2) * iL33;
        k0[3] = w3 * iL33;
        k0[2] = (w2 - L32*k0[3]) * iL22;
        k0[1] = (w1 - L21*k0[2] - L31*k0[3]) * iL11;
        k0[0] = (w0 - L10*k0[1] - L20*k0[2] - L30*k0[3]) * iL00;
    }
    {
        float w0 = a1[0] * iL00;
        float w1 = (a1[1] - L10*w0) * iL11;
        float w2 = (a1[2] - L20*w0 - L21*w1) * iL22;
        float w3 = (a1[3] - L30*w0 - L31*w1 - L32*w2) * iL33;
        k1[3] = w3 * iL33;
        k1[2] = (w2 - L32*k1[3]) * iL22;
        k1[1] = (w1 - L21*k1[2] - L31*k1[3]) * iL11;
        k1[0] = (w0 - L10*k1[1] - L20*k1[2] - L30*k1[3]) * iL00;
    }

    // ---- y = z - H @ x_pred (redundant) ----
    float xpv[8];
#pragma unroll
    for (int i = 0; i < 8; ++i) xpv[i] = XPb[i];
    float y[4];
#pragma unroll
    for (int m = 0; m < 4; ++m) {
        float acc = zb[m];
#pragma unroll
        for (int i = 0; i < 8; ++i) acc -= Hb[m*8+i] * xpv[i];
        y[m] = acc;
    }

    // ---- x_new own rows ----
    float xn0 = xp0, xn1 = xp1;
#pragma unroll
    for (int m = 0; m < 4; ++m) { xn0 += k0[m]*y[m]; xn1 += k1[m]*y[m]; }

    // ---- P_new rows: pn[r][j] = pp[r][j] - sum_m K[r][m]*HP[m][j] ----
    // write into sF region (F fully consumed); K into sQ; x_new into sx.
#pragma unroll
    for (int j = 0; j < 8; ++j) {
        float u0 = pp0[j], u1 = pp1[j];
#pragma unroll
        for (int m = 0; m < 4; ++m) {
            float hpmj = Ab[m*8+j];      // HP row m
            u0 -= k0[m] * hpmj; u1 -= k1[m] * hpmj;
        }
        Fb[r0*8+j] = u0; Fb[r1*8+j] = u1;
    }
#pragma unroll
    for (int m = 0; m < 4; ++m) { Qb[r0*4+m] = k0[m]; Qb[r1*4+m] = k1[m]; }
    xb[r0] = xn0; xb[r1] = xn1;

    __syncthreads();
    stage_out<8, 9>(out, sx, b0, tid);
    stage_out<64, 65>(out + (size_t)8 * BT, sF, b0, tid);
    stage_out<32, 65>(out + (size_t)72 * BT, sQ, b0, tid);
}

extern "C" void kernel_launch(void* const* d_in, const int* in_sizes, int n_in,
                              void* d_out, int out_size) {
    const float* x_est = (const float*)d_in[0];
    const float* P_est = (const float*)d_in[1];
    const float* F     = (const float*)d_in[2];
    const float* Q     = (const float*)d_in[3];
    const float* z     = (const float*)d_in[4];
    const float* H     = (const float*)d_in[5];
    const float* R     = (const float*)d_in[6];
    float* out = (float*)d_out;

    kf_kernel<<<BT / G, TPB>>>(x_est, P_est, F, Q, z, H, R, out);
}

// round 4
// speedup vs baseline: 1.6151x; 1.3943x over previous
#include <cuda_runtime.h>

// Batched Kalman filter: B=262144, N=8, M=4, fp32.
// 4 threads per batch (thread s owns rows {s, s+4}); all smem access is
// float4 (LDS.128/STS.128) on 16B-aligned odd-quad padded strides.
// Outputs flat: x_new[B,8], P_new[B,8,8], K[B,8,4].

constexpr int BT  = 262144;
constexpr int TPB = 128;
constexpr int G   = 32;          // batches per block
constexpr float EPS = 1e-6f;

// padded strides (floats): multiple of 4, (stride/4) odd -> aligned + conflict-free
constexpr int SF = 68;   // 64-float mats
constexpr int SH = 36;   // 32-float mats
constexpr int SR = 20;   // 16-float mats
constexpr int SX = 12;   // 8-float vecs
constexpr int SZ = 12;   // 4-float vecs (room to spare)

template<int E, int S>
__device__ __forceinline__ void stage_in(float* sm, const float* __restrict__ gp,
                                         int b0, int tid) {
    const float4* g4 = reinterpret_cast<const float4*>(gp + (size_t)b0 * E);
    constexpr int T4 = G * E / 4;
#pragma unroll
    for (int i = tid; i < T4; i += TPB) {
        float4 v = g4[i];
        int e = i * 4;
        *reinterpret_cast<float4*>(sm + (e / E) * S + (e % E)) = v;
    }
}

template<int E, int S>
__device__ __forceinline__ void stage_out(float* __restrict__ gp, const float* sm,
                                          int b0, int tid) {
    float4* g4 = reinterpret_cast<float4*>(gp + (size_t)b0 * E);
    constexpr int T4 = G * E / 4;
#pragma unroll
    for (int i = tid; i < T4; i += TPB) {
        int e = i * 4;
        g4[i] = *reinterpret_cast<const float4*>(sm + (e / E) * S + (e % E));
    }
}

__device__ __forceinline__ void ld_row8(float* d, const float* s) {
    float4 a = *reinterpret_cast<const float4*>(s);
    float4 b = *reinterpret_cast<const float4*>(s + 4);
    d[0]=a.x; d[1]=a.y; d[2]=a.z; d[3]=a.w;
    d[4]=b.x; d[5]=b.y; d[6]=b.z; d[7]=b.w;
}
__device__ __forceinline__ void st_row8(float* d, const float* s) {
    *reinterpret_cast<float4*>(d)     = make_float4(s[0], s[1], s[2], s[3]);
    *reinterpret_cast<float4*>(d + 4) = make_float4(s[4], s[5], s[6], s[7]);
}

__global__ __launch_bounds__(TPB, 5) void kf_kernel(
    const float* __restrict__ gx, const float* __restrict__ gP,
    const float* __restrict__ gF, const float* __restrict__ gQ,
    const float* __restrict__ gz, const float* __restrict__ gH,
    const float* __restrict__ gR, float* __restrict__ out)
{
    __shared__ __align__(16) float sm[9088];   // 36.4 KB
    float* sF = sm;                // G*68 = 2176
    float* sP = sm + 2176;         // 2176
    float* sQ = sm + 4352;         // 2176  (scratch after Q dead: A | S | XP)
    float* sH = sm + 6528;         // G*36 = 1152  (K output after H dead)
    float* sR = sm + 7680;         // G*20 = 640
    float* sx = sm + 8320;         // G*12 = 384
    float* sz = sm + 8704;         // G*12 = 384

    const int tid = threadIdx.x;
    const int b0  = blockIdx.x * G;
    const int g   = tid >> 2;
    const int s   = tid & 3;
    const int r0  = s, r1 = s + 4;

    stage_in<64, SF>(sF, gF, b0, tid);
    stage_in<8, SX>(sx, gx, b0, tid);
    stage_in<64, SF>(sP, gP, b0, tid);
    stage_in<64, SF>(sQ, gQ, b0, tid);
    stage_in<32, SH>(sH, gH, b0, tid);
    stage_in<16, SR>(sR, gR, b0, tid);
    stage_in<4, SZ>(sz, gz, b0, tid);
    __syncthreads();

    float* Fb = sF + g * SF;
    float* Pb = sP + g * SF;
    float* Qb = sQ + g * SF;
    float* Hb = sH + g * SH;
    float* Rb = sR + g * SR;
    float* xb = sx + g * SX;
    float* zb = sz + g * SZ;
    float* Ab  = Qb;               // [8][4] after Q dead; later HP [4][8]
    float* Sb  = Qb + 36;          // [4][4]
    float* XPb = Qb + 56;          // [8]

    // ---- own F rows ----
    float f0[8], f1[8];
    ld_row8(f0, Fb + r0 * 8);
    ld_row8(f1, Fb + r1 * 8);

    // ---- x_pred (own rows) ----
    float xv[8];
    ld_row8(xv, xb);
    float xp0 = 0.f, xp1 = 0.f;
#pragma unroll
    for (int j = 0; j < 8; ++j) { xp0 += f0[j]*xv[j]; xp1 += f1[j]*xv[j]; }

    // ---- T rows: T[r][:] = sum_k F[r][k] * P[k][:] ----
    float t0[8], t1[8];
#pragma unroll
    for (int j = 0; j < 8; ++j) { t0[j] = 0.f; t1[j] = 0.f; }
#pragma unroll
    for (int k = 0; k < 8; ++k) {
        float pr[8];
        ld_row8(pr, Pb + k * 8);
        float fk0 = f0[k], fk1 = f1[k];
#pragma unroll
        for (int j = 0; j < 8; ++j) { t0[j] += fk0 * pr[j]; t1[j] += fk1 * pr[j]; }
    }

    // ---- P_pred rows: pp[r][j] = sum_k T[r][k]*F[j][k] + Q[r][j] ----
    float pp0[8], pp1[8];
    {
        float q0[8], q1[8];
        ld_row8(q0, Qb + r0 * 8);
        ld_row8(q1, Qb + r1 * 8);
#pragma unroll
        for (int j = 0; j < 8; ++j) {
            float fr[8];
            ld_row8(fr, Fb + j * 8);
            float u0 = q0[j], u1 = q1[j];
#pragma unroll
            for (int k = 0; k < 8; ++k) { u0 += t0[k]*fr[k]; u1 += t1[k]*fr[k]; }
            pp0[j] = u0; pp1[j] = u1;
        }
    }

    // ---- A rows: A[r][m] = sum_j pp[r][j] * H[m][j] ----
    float a0[4], a1[4];
#pragma unroll
    for (int m = 0; m < 4; ++m) {
        float hr[8];
        ld_row8(hr, Hb + m * 8);
        float u0 = 0.f, u1 = 0.f;
#pragma unroll
        for (int j = 0; j < 8; ++j) { u0 += pp0[j]*hr[j]; u1 += pp1[j]*hr[j]; }
        a0[m] = u0; a1[m] = u1;
    }

    // ---- publish pp (into sP), A, xp (A/XP overlay Q region) ----
    __syncwarp();                  // group done reading P, x, F, Q
    st_row8(Pb + r0 * 8, pp0);
    st_row8(Pb + r1 * 8, pp1);
    *reinterpret_cast<float4*>(Ab + r0 * 4) = make_float4(a0[0], a0[1], a0[2], a0[3]);
    *reinterpret_cast<float4*>(Ab + r1 * 4) = make_float4(a1[0], a1[1], a1[2], a1[3]);
    XPb[r0] = xp0; XPb[r1] = xp1;
    __syncwarp();                  // publish

    // ---- S row s = R row + eps*e_s + sum_i H[s][i]*A[i][:] ----
    float hs[8];
    ld_row8(hs, Hb + s * 8);
    {
        float4 rr = *reinterpret_cast<const float4*>(Rb + s * 4);
        float acc[4] = {rr.x, rr.y, rr.z, rr.w};
        acc[s] += EPS;
#pragma unroll
        for (int i = 0; i < 8; ++i) {
            float4 ar = *reinterpret_cast<const float4*>(Ab + i * 4);
            float hi = hs[i];
            acc[0] += hi * ar.x; acc[1] += hi * ar.y;
            acc[2] += hi * ar.z; acc[3] += hi * ar.w;
        }
        *reinterpret_cast<float4*>(Sb + s * 4) = make_float4(acc[0], acc[1], acc[2], acc[3]);
    }

    // ---- HP row s = sum_i H[s][i] * P_pred[i][:] ----
    float hprow[8];
#pragma unroll
    for (int j = 0; j < 8; ++j) hprow[j] = 0.f;
#pragma unroll
    for (int i = 0; i < 8; ++i) {
        float pr[8];
        ld_row8(pr, Pb + i * 8);
        float hi = hs[i];
#pragma unroll
        for (int j = 0; j < 8; ++j) hprow[j] += hi * pr[j];
    }
    __syncwarp();                  // all A reads (S loop) done -> overlay HP on A
    st_row8(Ab + s * 8, hprow);    // HP row s
    __syncwarp();                  // publish S + HP

    // ---- Cholesky of S (redundant per thread) ----
    float4 S0 = *reinterpret_cast<const float4*>(Sb);
    float4 S1 = *reinterpret_cast<const float4*>(Sb + 4);
    float4 S2 = *reinterpret_cast<const float4*>(Sb + 8);
    float4 S3 = *reinterpret_cast<const float4*>(Sb + 12);

    float iL00 = rsqrtf(S0.x);
    float L10 = S1.x * iL00, L20 = S2.x * iL00, L30 = S3.x * iL00;
    float iL11 = rsqrtf(S1.y - L10*L10);
    float L21 = (S2.y - L20*L10) * iL11;
    float L31 = (S3.y - L30*L10) * iL11;
    float iL22 = rsqrtf(S2.z - L20*L20 - L21*L21);
    float L32 = (S3.z - L30*L20 - L31*L21) * iL22;
    float iL33 = rsqrtf(S3.w - L30*L30 - L31*L31 - L32*L32);

    // ---- K rows (own): solve S k = a ----
    float k0[4], k1[4];
    {
        float w0 = a0[0] * iL00;
        float w1 = (a0[1] - L10*w0) * iL11;
        float w2 = (a0[2] - L20*w0 - L21*w1) * iL22;
        float w3 = (a0[3] - L30*w0 - L31*w1 - L32*w2) * iL33;
        k0[3] = w3 * iL33;
        k0[2] = (w2 - L32*k0[3]) * iL22;
        k0[1] = (w1 - L21*k0[2] - L31*k0[3]) * iL11;
        k0[0] = (w0 - L10*k0[1] - L20*k0[2] - L30*k0[3]) * iL00;
    }
    {
        float w0 = a1[0] * iL00;
        float w1 = (a1[1] - L10*w0) * iL11;
        float w2 = (a1[2] - L20*w0 - L21*w1) * iL22;
        float w3 = (a1[3] - L30*w0 - L31*w1 - L32*w2) * iL33;
        k1[3] = w3 * iL33;
        k1[2] = (w2 - L32*k1[3]) * iL22;
        k1[1] = (w1 - L21*k1[2] - L31*k1[3]) * iL11;
        k1[0] = (w0 - L10*k1[1] - L20*k1[2] - L30*k1[3]) * iL00;
    }

    // ---- y = z - H @ x_pred (redundant per thread) ----
    float xpv[8];
    ld_row8(xpv, XPb);
    float4 zz = *reinterpret_cast<const float4*>(zb);
    float y[4] = {zz.x, zz.y, zz.z, zz.w};
#pragma unroll
    for (int m = 0; m < 4; ++m) {
        float hr[8];
        ld_row8(hr, Hb + m * 8);
        float acc = y[m];
#pragma unroll
        for (int i = 0; i < 8; ++i) acc -= hr[i] * xpv[i];
        y[m] = acc;
    }

    // ---- x_new own rows ----
    float xn0 = xp0, xn1 = xp1;
#pragma unroll
    for (int m = 0; m < 4; ++m) { xn0 += k0[m]*y[m]; xn1 += k1[m]*y[m]; }

    // ---- P_new rows: pn[r][:] = pp[r][:] - sum_m K[r][m]*HP[m][:] ----
    float hp[32];
#pragma unroll
    for (int m = 0; m < 4; ++m) ld_row8(hp + m * 8, Ab + m * 8);

    float pn0[8], pn1[8];
#pragma unroll
    for (int j = 0; j < 8; ++j) {
        float u0 = pp0[j], u1 = pp1[j];
#pragma unroll
        for (int m = 0; m < 4; ++m) {
            float hpmj = hp[m*8+j];
            u0 -= k0[m] * hpmj; u1 -= k1[m] * hpmj;
        }
        pn0[j] = u0; pn1[j] = u1;
    }

    // ---- stores: P_new -> sF (F dead), x_new -> sx (x dead), K -> sH (H dead)
    st_row8(Fb + r0 * 8, pn0);
    st_row8(Fb + r1 * 8, pn1);
    xb[r0] = xn0; xb[r1] = xn1;
    __syncwarp();                  // all H reads done before K overwrites it
    *reinterpret_cast<float4*>(Hb + r0 * 4) = make_float4(k0[0], k0[1], k0[2], k0[3]);
    *reinterpret_cast<float4*>(Hb + r1 * 4) = make_float4(k1[0], k1[1], k1[2], k1[3]);

    __syncthreads();
    stage_out<8, SX>(out, sx, b0, tid);
    stage_out<64, SF>(out + (size_t)8 * BT, sF, b0, tid);
    stage_out<32, SH>(out + (size_t)72 * BT, sH, b0, tid);
}

extern "C" void kernel_launch(void* const* d_in, const int* in_sizes, int n_in,
                              void* d_out, int out_size) {
    const float* x_est = (const float*)d_in[0];
    const float* P_est = (const float*)d_in[1];
    const float* F     = (const float*)d_in[2];
    const float* Q     = (const float*)d_in[3];
    const float* z     = (const float*)d_in[4];
    const float* H     = (const float*)d_in[5];
    const float* R     = (const float*)d_in[6];
    float* out = (float*)d_out;

    kf_kernel<<<BT / G, TPB>>>(x_est, P_est, F, Q, z, H, R, out);
}

// round 5
// speedup vs baseline: 1.6159x; 1.0005x over previous
#include <cuda_runtime.h>

// Batched Kalman filter: B=262144, N=8, M=4, fp32.
// 4 threads per batch (thread s owns rows {s, s+4}); float4 smem throughout.
// Uses P_pred symmetry: HP = A^T (A = P_pred H^T), eliminating the HP pass.
// Innovation y computed distributed (thread s -> y[s]).
// Outputs flat: x_new[B,8], P_new[B,8,8], K[B,8,4].

constexpr int BT  = 262144;
constexpr int TPB = 128;
constexpr int G   = 32;
constexpr float EPS = 1e-6f;

constexpr int SF = 68;
constexpr int SH = 36;
constexpr int SR = 20;
constexpr int SX = 12;
constexpr int SZ = 12;

template<int E, int S>
__device__ __forceinline__ void stage_in(float* sm, const float* __restrict__ gp,
                                         int b0, int tid) {
    const float4* g4 = reinterpret_cast<const float4*>(gp + (size_t)b0 * E);
    constexpr int T4 = G * E / 4;
#pragma unroll
    for (int i = tid; i < T4; i += TPB) {
        float4 v = g4[i];
        int e = i * 4;
        *reinterpret_cast<float4*>(sm + (e / E) * S + (e % E)) = v;
    }
}

template<int E, int S>
__device__ __forceinline__ void stage_out(float* __restrict__ gp, const float* sm,
                                          int b0, int tid) {
    float4* g4 = reinterpret_cast<float4*>(gp + (size_t)b0 * E);
    constexpr int T4 = G * E / 4;
#pragma unroll
    for (int i = tid; i < T4; i += TPB) {
        int e = i * 4;
        g4[i] = *reinterpret_cast<const float4*>(sm + (e / E) * S + (e % E));
    }
}

__device__ __forceinline__ void ld_row8(float* d, const float* s) {
    float4 a = *reinterpret_cast<const float4*>(s);
    float4 b = *reinterpret_cast<const float4*>(s + 4);
    d[0]=a.x; d[1]=a.y; d[2]=a.z; d[3]=a.w;
    d[4]=b.x; d[5]=b.y; d[6]=b.z; d[7]=b.w;
}
__device__ __forceinline__ void st_row8(float* d, const float* s) {
    *reinterpret_cast<float4*>(d)     = make_float4(s[0], s[1], s[2], s[3]);
    *reinterpret_cast<float4*>(d + 4) = make_float4(s[4], s[5], s[6], s[7]);
}

__global__ __launch_bounds__(TPB, 5) void kf_kernel(
    const float* __restrict__ gx, const float* __restrict__ gP,
    const float* __restrict__ gF, const float* __restrict__ gQ,
    const float* __restrict__ gz, const float* __restrict__ gH,
    const float* __restrict__ gR, float* __restrict__ out)
{
    __shared__ __align__(16) float sm[9088];   // 36.4 KB
    float* sF = sm;                // G*68
    float* sP = sm + 2176;
    float* sQ = sm + 4352;         // scratch after Q dead: A | S | XP | y
    float* sH = sm + 6528;         // K output after H dead
    float* sR = sm + 7680;
    float* sx = sm + 8320;
    float* sz = sm + 8704;

    const int tid = threadIdx.x;
    const int b0  = blockIdx.x * G;
    const int g   = tid >> 2;
    const int s   = tid & 3;
    const int r0  = s, r1 = s + 4;

    stage_in<64, SF>(sF, gF, b0, tid);
    stage_in<8, SX>(sx, gx, b0, tid);
    stage_in<64, SF>(sP, gP, b0, tid);
    stage_in<64, SF>(sQ, gQ, b0, tid);
    stage_in<32, SH>(sH, gH, b0, tid);
    stage_in<16, SR>(sR, gR, b0, tid);
    stage_in<4, SZ>(sz, gz, b0, tid);
    __syncthreads();

    float* Fb = sF + g * SF;
    float* Pb = sP + g * SF;
    float* Qb = sQ + g * SF;
    float* Hb = sH + g * SH;
    float* Rb = sR + g * SR;
    float* xb = sx + g * SX;
    float* zb = sz + g * SZ;
    float* Ab  = Qb;               // A [8][4] (row i at +4i), overlays dead Q
    float* Sb  = Qb + 36;          // S [4][4]
    float* XPb = Qb + 52;          // x_pred [8]
    float* Yb  = Qb + 60;          // y [4]

    // ---- own F rows; x_pred ----
    float f0[8], f1[8];
    ld_row8(f0, Fb + r0 * 8);
    ld_row8(f1, Fb + r1 * 8);
    float xv[8];
    ld_row8(xv, xb);
    float xp0 = 0.f, xp1 = 0.f;
#pragma unroll
    for (int j = 0; j < 8; ++j) { xp0 += f0[j]*xv[j]; xp1 += f1[j]*xv[j]; }

    // ---- T rows ----
    float t0[8], t1[8];
#pragma unroll
    for (int j = 0; j < 8; ++j) { t0[j] = 0.f; t1[j] = 0.f; }
#pragma unroll
    for (int k = 0; k < 8; ++k) {
        float pr[8];
        ld_row8(pr, Pb + k * 8);
        float fk0 = f0[k], fk1 = f1[k];
#pragma unroll
        for (int j = 0; j < 8; ++j) { t0[j] += fk0 * pr[j]; t1[j] += fk1 * pr[j]; }
    }

    // ---- P_pred rows ----
    float pp0[8], pp1[8];
    {
        float q0[8], q1[8];
        ld_row8(q0, Qb + r0 * 8);
        ld_row8(q1, Qb + r1 * 8);
#pragma unroll
        for (int j = 0; j < 8; ++j) {
            float fr[8];
            ld_row8(fr, Fb + j * 8);
            float u0 = q0[j], u1 = q1[j];
#pragma unroll
            for (int k = 0; k < 8; ++k) { u0 += t0[k]*fr[k]; u1 += t1[k]*fr[k]; }
            pp0[j] = u0; pp1[j] = u1;
        }
    }

    // ---- A rows: A[r][m] = pp[r] . H[m] ----
    float a0[4], a1[4];
#pragma unroll
    for (int m = 0; m < 4; ++m) {
        float hr[8];
        ld_row8(hr, Hb + m * 8);
        float u0 = 0.f, u1 = 0.f;
#pragma unroll
        for (int j = 0; j < 8; ++j) { u0 += pp0[j]*hr[j]; u1 += pp1[j]*hr[j]; }
        a0[m] = u0; a1[m] = u1;
    }

    // ---- publish pp, A, xp ----
    __syncwarp();
    st_row8(Pb + r0 * 8, pp0);
    st_row8(Pb + r1 * 8, pp1);
    *reinterpret_cast<float4*>(Ab + r0 * 4) = make_float4(a0[0], a0[1], a0[2], a0[3]);
    *reinterpret_cast<float4*>(Ab + r1 * 4) = make_float4(a1[0], a1[1], a1[2], a1[3]);
    XPb[r0] = xp0; XPb[r1] = xp1;
    __syncwarp();

    // ---- S row s (needs H row s + full A) ; y[s] distributed ----
    float hs[8];
    ld_row8(hs, Hb + s * 8);
    {
        float4 rr = *reinterpret_cast<const float4*>(Rb + s * 4);
        float ac0 = rr.x + (s == 0 ? EPS : 0.f);
        float ac1 = rr.y + (s == 1 ? EPS : 0.f);
        float ac2 = rr.z + (s == 2 ? EPS : 0.f);
        float ac3 = rr.w + (s == 3 ? EPS : 0.f);
#pragma unroll
        for (int i = 0; i < 8; ++i) {
            float4 ar = *reinterpret_cast<const float4*>(Ab + i * 4);
            float hi = hs[i];
            ac0 += hi * ar.x; ac1 += hi * ar.y;
            ac2 += hi * ar.z; ac3 += hi * ar.w;
        }
        *reinterpret_cast<float4*>(Sb + s * 4) = make_float4(ac0, ac1, ac2, ac3);
    }
    {
        float xpv[8];
        ld_row8(xpv, XPb);
        float acc = zb[s];
#pragma unroll
        for (int i = 0; i < 8; ++i) acc -= hs[i] * xpv[i];
        Yb[s] = acc;
    }
    __syncwarp();

    // ---- Cholesky of S (redundant per thread) ----
    float4 S0 = *reinterpret_cast<const float4*>(Sb);
    float4 S1 = *reinterpret_cast<const float4*>(Sb + 4);
    float4 S2 = *reinterpret_cast<const float4*>(Sb + 8);
    float4 S3 = *reinterpret_cast<const float4*>(Sb + 12);

    float iL00 = rsqrtf(S0.x);
    float L10 = S1.x * iL00, L20 = S2.x * iL00, L30 = S3.x * iL00;
    float iL11 = rsqrtf(S1.y - L10*L10);
    float L21 = (S2.y - L20*L10) * iL11;
    float L31 = (S3.y - L30*L10) * iL11;
    float iL22 = rsqrtf(S2.z - L20*L20 - L21*L21);
    float L32 = (S3.z - L30*L20 - L31*L21) * iL22;
    float iL33 = rsqrtf(S3.w - L30*L30 - L31*L31 - L32*L32);

    // ---- K rows (own): solve S k = a ----
    float k0[4], k1[4];
    {
        float w0 = a0[0] * iL00;
        float w1 = (a0[1] - L10*w0) * iL11;
        float w2 = (a0[2] - L20*w0 - L21*w1) * iL22;
        float w3 = (a0[3] - L30*w0 - L31*w1 - L32*w2) * iL33;
        k0[3] = w3 * iL33;
        k0[2] = (w2 - L32*k0[3]) * iL22;
        k0[1] = (w1 - L21*k0[2] - L31*k0[3]) * iL11;
        k0[0] = (w0 - L10*k0[1] - L20*k0[2] - L30*k0[3]) * iL00;
    }
    {
        float w0 = a1[0] * iL00;
        float w1 = (a1[1] - L10*w0) * iL11;
        float w2 = (a1[2] - L20*w0 - L21*w1) * iL22;
        float w3 = (a1[3] - L30*w0 - L31*w1 - L32*w2) * iL33;
        k1[3] = w3 * iL33;
        k1[2] = (w2 - L32*k1[3]) * iL22;
        k1[1] = (w1 - L21*k1[2] - L31*k1[3]) * iL11;
        k1[0] = (w0 - L10*k1[1] - L20*k1[2] - L30*k1[3]) * iL00;
    }

    // ---- x_new own rows (y from smem) ----
    float4 yv = *reinterpret_cast<const float4*>(Yb);
    float y[4] = {yv.x, yv.y, yv.z, yv.w};
    float xn0 = xp0, xn1 = xp1;
#pragma unroll
    for (int m = 0; m < 4; ++m) { xn0 += k0[m]*y[m]; xn1 += k1[m]*y[m]; }

    // ---- P_new rows: pn[r][j] = pp[r][j] - sum_m K[r][m]*A[j][m]  (HP = A^T) ----
    float pn0[8], pn1[8];
#pragma unroll
    for (int j = 0; j < 8; ++j) {
        float4 ar = *reinterpret_cast<const float4*>(Ab + j * 4);
        float u0 = pp0[j], u1 = pp1[j];
        u0 -= k0[0]*ar.x + k0[1]*ar.y + k0[2]*ar.z + k0[3]*ar.w;
        u1 -= k1[0]*ar.x + k1[1]*ar.y + k1[2]*ar.z + k1[3]*ar.w;
        pn0[j] = u0; pn1[j] = u1;
    }

    // ---- stores: P_new -> sF (F dead), x_new -> sx, K -> sH (H dead) ----
    st_row8(Fb + r0 * 8, pn0);
    st_row8(Fb + r1 * 8, pn1);
    xb[r0] = xn0; xb[r1] = xn1;
    *reinterpret_cast<float4*>(Hb + r0 * 4) = make_float4(k0[0], k0[1], k0[2], k0[3]);
    *reinterpret_cast<float4*>(Hb + r1 * 4) = make_float4(k1[0], k1[1], k1[2], k1[3]);

    __syncthreads();
    stage_out<8, SX>(out, sx, b0, tid);
    stage_out<64, SF>(out + (size_t)8 * BT, sF, b0, tid);
    stage_out<32, SH>(out + (size_t)72 * BT, sH, b0, tid);
}

extern "C" void kernel_launch(void* const* d_in, const int* in_sizes, int n_in,
                              void* d_out, int out_size) {
    const float* x_est = (const float*)d_in[0];
    const float* P_est = (const float*)d_in[1];
    const float* F     = (const float*)d_in[2];
    const float* Q     = (const float*)d_in[3];
    const float* z     = (const float*)d_in[4];
    const float* H     = (const float*)d_in[5];
    const float* R     = (const float*)d_in[6];
    float* out = (float*)d_out;

    kf_kernel<<<BT / G, TPB>>>(x_est, P_est, F, Q, z, H, R, out);
}